// round 3
// baseline (speedup 1.0000x reference)
#include <cuda_runtime.h>
#include <cuda_bf16.h>
#include <cstdint>

// Embedding gather: out[r, :] = table[indices[r], :]
// n_rows = B*F = 819200, D = 64 floats (256 B per row).
//
// Layout: 16 threads per row (one float4 each). Each thread handles
// RPT=8 rows with front-batched independent loads (MLP=8 per thread).
// Output stores use .cs (evict-first) so the write-once output doesn't
// displace table rows from L2.

static constexpr int D = 64;                // embedding dim (floats)
static constexpr int LANES = 16;            // D/4 float4 lanes per row
static constexpr int RPT = 8;               // rows per thread
static constexpr int BLOCK = 256;
static constexpr int ROWS_PER_BLOCK = (BLOCK / LANES) * RPT;  // 128

__global__ __launch_bounds__(BLOCK)
void gather_kernel(const int* __restrict__ indices,
                   const float* __restrict__ table,
                   float* __restrict__ out,
                   int n_rows)
{
    const int local_row = threadIdx.x >> 4;   // 0..15
    const int lane      = threadIdx.x & 15;   // 0..15
    const long long row_base = (long long)blockIdx.x * ROWS_PER_BLOCK + local_row;

    int    idx[RPT];
    float4 vals[RPT];

    // Phase 1: batched independent index loads (coalesced, L1-broadcast
    // across the 16 lanes of a lane-group)
#pragma unroll
    for (int k = 0; k < RPT; k++) {
        const long long r = row_base + (long long)k * LANES;
        idx[k] = (r < n_rows) ? __ldg(indices + r) : 0;
    }

    // Phase 2: batched independent table gathers (MLP = RPT)
#pragma unroll
    for (int k = 0; k < RPT; k++) {
        const float4* src =
            reinterpret_cast<const float4*>(table + (long long)idx[k] * D) + lane;
        vals[k] = __ldg(src);
    }

    // Phase 3: streaming stores (evict-first; output is write-once)
#pragma unroll
    for (int k = 0; k < RPT; k++) {
        const long long r = row_base + (long long)k * LANES;
        if (r < n_rows) {
            float4* dst = reinterpret_cast<float4*>(out + r * D) + lane;
            __stcs(dst, vals[k]);
        }
    }
}

extern "C" void kernel_launch(void* const* d_in, const int* in_sizes, int n_in,
                              void* d_out, int out_size)
{
    const int*   indices = (const int*)d_in[0];
    const float* table   = (const float*)d_in[1];
    float*       out     = (float*)d_out;

    const int n_rows = in_sizes[0];            // B*F = 819200
    const int grid   = (n_rows + ROWS_PER_BLOCK - 1) / ROWS_PER_BLOCK;

    gather_kernel<<<grid, BLOCK>>>(indices, table, out, n_rows);
}

// round 4
// speedup vs baseline: 1.0015x; 1.0015x over previous
#include <cuda_runtime.h>
#include <cuda_bf16.h>
#include <cstdint>

// Embedding gather: out[r, :] = table[indices[r], :]
// n_rows = B*F = 819200, D = 64 floats (256 B per row).
//
// Strategy: cp.async.cg (LDGSTS) gather into shared memory. LDGSTS has no
// destination register and no scoreboard dependency, so ALL 1024 16-byte
// chunk loads of a block are outstanding simultaneously (register-resident
// batching capped at MLP_eff~2-3 because ptxas refuses to hold 8 float4 in
// regs). One wait, then fully-coalesced float4 streaming stores to out.

static constexpr int D       = 64;          // embedding dim (floats)
static constexpr int BLOCK   = 256;
static constexpr int ROWS    = 64;          // rows per block
static constexpr int CHUNKS  = ROWS * 16;   // 16B chunks per block = 1024
static constexpr int CPT     = CHUNKS / BLOCK;  // chunks per thread = 4

__global__ __launch_bounds__(BLOCK)
void gather_kernel(const int* __restrict__ indices,
                   const float* __restrict__ table,
                   float* __restrict__ out,
                   int n_rows)
{
    __shared__ float4 buf[CHUNKS];          // 16 KB staging buffer

    const long long row_base = (long long)blockIdx.x * ROWS;
    const uint32_t  s_base   = (uint32_t)__cvta_generic_to_shared(buf);

    // Phase 1: fire-and-forget async gather. chunk c -> row c/16, lane c%16.
    // Consecutive threads cover consecutive lanes: each 16-thread group reads
    // one contiguous 256B table row; smem writes are linear (conflict-free).
#pragma unroll
    for (int k = 0; k < CPT; k++) {
        const int c    = threadIdx.x + k * BLOCK;
        const int lane = c & 15;
        const long long row = row_base + (c >> 4);
        const int idx = (row < n_rows) ? __ldg(indices + row) : 0;

        const float4* src =
            reinterpret_cast<const float4*>(table + (long long)idx * D) + lane;
        const uint32_t dst = s_base + (uint32_t)c * 16u;

        asm volatile("cp.async.cg.shared.global [%0], [%1], 16;\n"
                     :: "r"(dst), "l"(src) : "memory");
    }
    asm volatile("cp.async.commit_group;\n" ::: "memory");
    asm volatile("cp.async.wait_group 0;\n" ::: "memory");
    __syncthreads();

    // Phase 2: coalesced streaming stores (evict-first; output is write-once).
    // out chunk index for block = row_base*16 + c (float4 units).
#pragma unroll
    for (int k = 0; k < CPT; k++) {
        const int c = threadIdx.x + k * BLOCK;
        const long long row = row_base + (c >> 4);
        if (row < n_rows) {
            float4* dst = reinterpret_cast<float4*>(out) + row_base * 16 + c;
            __stcs(dst, buf[c]);
        }
    }
}

extern "C" void kernel_launch(void* const* d_in, const int* in_sizes, int n_in,
                              void* d_out, int out_size)
{
    const int*   indices = (const int*)d_in[0];
    const float* table   = (const float*)d_in[1];
    float*       out     = (float*)d_out;

    const int n_rows = in_sizes[0];            // B*F = 819200
    const int grid   = (n_rows + ROWS - 1) / ROWS;

    gather_kernel<<<grid, BLOCK>>>(indices, table, out, n_rows);
}